// round 15
// baseline (speedup 1.0000x reference)
#include <cuda_runtime.h>
#include <cuda_bf16.h>
#include <math.h>

#define B_SZ 4
#define LSEQ 512
#define DM   1024
#define ED   2048
#define NS   16
#define DTR  64
#define KX   96                 // DTR + 2*NS
#define MROWS (B_SZ*LSEQ)       // 2048
#define SPLITS 8
#define NED   ((size_t)MROWS * ED)
#define NDBC  ((size_t)MROWS * KX)
#define NOUT  ((size_t)MROWS * DM)

#define N_X    ((size_t)MROWS * DM)
#define N_WIN  ((size_t)2 * ED * DM)
#define N_WX   ((size_t)KX * ED)
#define N_WDT  ((size_t)ED * DTR)
#define N_WOUT ((size_t)DM * ED)

// ---------------- scratch (static device globals; no runtime allocation) ----
__device__ __align__(16) float g_xz   [(size_t)MROWS * 2 * ED];
__device__ __align__(16) float g_xconv[2 * NED];
__device__ __align__(16) float g_dbc  [2 * NDBC];
__device__ __align__(16) float g_dbcp [2 * (size_t)SPLITS * NDBC];
__device__ __align__(16) float g_delta[2 * NED];   // reused post-scan for out partials
__device__ __align__(16) float g_y    [2 * NED];

// bf16 hi/lo split operands
__device__ __align__(16) __nv_bfloat16 g_xh[N_X],     g_xl[N_X];
__device__ __align__(16) __nv_bfloat16 g_Winh[N_WIN], g_Winl[N_WIN];
__device__ __align__(16) __nv_bfloat16 g_Wxh[2*N_WX], g_Wxl[2*N_WX];
__device__ __align__(16) __nv_bfloat16 g_Wdth[2*N_WDT], g_Wdtl[2*N_WDT];
__device__ __align__(16) __nv_bfloat16 g_Wouth[N_WOUT], g_Woutl[N_WOUT];
__device__ __align__(16) __nv_bfloat16 g_xch[2*NED], g_xcl[2*NED];
__device__ __align__(16) __nv_bfloat16 g_dbch[2*NDBC], g_dbcl[2*NDBC];
__device__ __align__(16) __nv_bfloat16 g_ych[NED], g_ycl[NED];

__device__ __forceinline__ float sigmoidf_(float v) {
    return 1.f / (1.f + __expf(-v));
}

__device__ __forceinline__ void s1(float v, __nv_bfloat16& h, __nv_bfloat16& l) {
    h = __float2bfloat16(v);
    l = __float2bfloat16(v - __bfloat162float(h));
}

// bf16 m16n8k16 MMA (row.col), fp32 accumulate in-place.
__device__ __forceinline__ void mma_bf16(float c[4],
                                         unsigned a0, unsigned a1,
                                         unsigned a2, unsigned a3,
                                         unsigned b0, unsigned b1)
{
    asm volatile(
        "mma.sync.aligned.m16n8k16.row.col.f32.bf16.bf16.f32 "
        "{%0,%1,%2,%3}, {%4,%5,%6,%7}, {%8,%9}, {%0,%1,%2,%3};\n"
        : "+f"(c[0]), "+f"(c[1]), "+f"(c[2]), "+f"(c[3])
        : "r"(a0), "r"(a1), "r"(a2), "r"(a3), "r"(b0), "r"(b1));
}

__device__ __forceinline__ void ldsm_x4(unsigned& r0, unsigned& r1,
                                        unsigned& r2, unsigned& r3, unsigned a)
{
    asm volatile("ldmatrix.sync.aligned.m8n8.x4.shared.b16 {%0,%1,%2,%3}, [%4];"
                 : "=r"(r0), "=r"(r1), "=r"(r2), "=r"(r3) : "r"(a));
}

__device__ __forceinline__ void ldsm_x2(unsigned& r0, unsigned& r1, unsigned a)
{
    asm volatile("ldmatrix.sync.aligned.m8n8.x2.shared.b16 {%0,%1}, [%2];"
                 : "=r"(r0), "=r"(r1) : "r"(a));
}

__device__ __forceinline__ void cpa16(unsigned saddr, const void* g, bool v) {
    asm volatile("cp.async.ca.shared.global [%0], [%1], 16, %2;\n"
                 :: "r"(saddr), "l"(g), "r"(v ? 16 : 0));
}

// ---------------------------------------------------------------------------
// Tensor-core NT GEMM, pre-split bf16 (3-MMA compensated) — R12 schedule.
// BM=BN=128, BK=32, 256 threads = 8 warps (2x4), warp tile 64x32.
// 2-stage cp.async double buffer; ldmatrix fragment loads.
// __launch_bounds__(256,2): cap regs at 128 so 2 CTAs/SM co-reside.
// blockIdx.z = dir*zdiv + split s. epi1 = softplus(v+bias[n]).
// ---------------------------------------------------------------------------
__global__ __launch_bounds__(256, 2) void tgemm_bf16(
    const __nv_bfloat16* __restrict__ Ahp, const __nv_bfloat16* __restrict__ Alp,
    int lda, size_t sAdir,
    const __nv_bfloat16* __restrict__ Bh0, const __nv_bfloat16* __restrict__ Bl0,
    const __nv_bfloat16* __restrict__ Bh1, const __nv_bfloat16* __restrict__ Bl1,
    int ldb,
    float* __restrict__ C, int ldc, size_t sCdir,
    int M, int N, int Ktot, int ksz, int zdiv,
    int epi, const float* __restrict__ bias0, const float* __restrict__ bias1)
{
    extern __shared__ unsigned smem[];   // 2 x 32KB

    const int bm  = blockIdx.y * 128;
    const int bn  = blockIdx.x * 128;
    const int dir = blockIdx.z / zdiv;
    const int s   = blockIdx.z % zdiv;
    const int k0  = s * ksz;
    int k1 = k0 + ksz; if (k1 > Ktot) k1 = Ktot;
    const int T = (k1 - k0) >> 5;        // BK=32 tiles

    const __nv_bfloat16* Ah = Ahp + (size_t)dir * sAdir;
    const __nv_bfloat16* Al = Alp + (size_t)dir * sAdir;
    const __nv_bfloat16* Bh = dir ? Bh1 : Bh0;
    const __nv_bfloat16* Bl = dir ? Bl1 : Bl0;
    const float* bias = dir ? bias1 : bias0;
    float* Cout = C + (size_t)dir * sCdir + (size_t)s * (size_t)M * (size_t)ldc;

    const int tid  = threadIdx.x;
    const int warp = tid >> 5, lane = tid & 31;
    const int wm = (warp >> 2) * 64;
    const int wn = (warp & 3) * 32;
    const int qr = lane >> 2;            // 0..7
    const int qc = lane & 3;             // 0..3

    unsigned sbase = (unsigned)__cvta_generic_to_shared(smem);

    auto stage = [&](int kbase, int buf) {
        unsigned base = sbase + buf * 32768;
#pragma unroll
        for (int u = tid; u < 512; u += 256) {
            int row = u >> 2, grp = u & 3;
            int gp = grp ^ ((row >> 1) & 3);
            unsigned so = base + (unsigned)(row * 64 + gp * 16);
            const size_t ka = (size_t)(bm + row) * lda + kbase + grp * 8;
            cpa16(so,          Ah + ka, true);
            cpa16(so +  8192,  Al + ka, true);
            bool bv = (bn + row) < N;
            const size_t kb = (size_t)(bn + row) * ldb + kbase + grp * 8;
            cpa16(so + 16384,  Bh + kb, bv);
            cpa16(so + 24576,  Bl + kb, bv);
        }
        asm volatile("cp.async.commit_group;\n");
    };

    // precomputed ldmatrix byte offsets (within one operand array, kk=0)
    unsigned aoff[4], boff[4];
#pragma unroll
    for (int i = 0; i < 4; i++) {
        int row = wm + i * 16 + (lane & 15);
        int ch  = lane >> 4;                      // 0: k0-7, 1: k8-15
        int g   = ch ^ ((row >> 1) & 3);
        aoff[i] = (unsigned)(row * 64 + g * 16);
    }
#pragma unroll
    for (int j = 0; j < 4; j++) {
        int row = wn + j * 8 + (lane & 7);
        int ch  = (lane >> 3) & 1;
        int g   = ch ^ ((row >> 1) & 3);
        boff[j] = (unsigned)(row * 64 + g * 16);
    }

    float acc[4][4][4];
#pragma unroll
    for (int i = 0; i < 4; i++)
#pragma unroll
        for (int j = 0; j < 4; j++)
#pragma unroll
            for (int r = 0; r < 4; r++) acc[i][j][r] = 0.f;

    stage(k0, 0);

    for (int t = 0; t < T; t++) {
        const int nxt = (t + 1 < T) ? t + 1 : t;
        stage(k0 + nxt * 32, (t + 1) & 1);
        asm volatile("cp.async.wait_group 1;\n");
        __syncthreads();

        const unsigned Ab = sbase + (t & 1) * 32768;

#pragma unroll
        for (int kk = 0; kk < 2; kk++) {
            const unsigned kx = kk * 32;          // chunk 0/1 -> 2/3 via XOR
            unsigned bh0[4], bh1[4], bl0[4], bl1[4];
#pragma unroll
            for (int j = 0; j < 4; j++) {
                ldsm_x2(bh0[j], bh1[j], Ab + 16384 + (boff[j] ^ kx));
                ldsm_x2(bl0[j], bl1[j], Ab + 24576 + (boff[j] ^ kx));
            }
#pragma unroll
            for (int i = 0; i < 4; i++) {
                unsigned ah0, ah1, ah2, ah3, al0, al1, al2, al3;
                ldsm_x4(ah0, ah1, ah2, ah3, Ab + (aoff[i] ^ kx));
                ldsm_x4(al0, al1, al2, al3, Ab + 8192 + (aoff[i] ^ kx));
#pragma unroll
                for (int j = 0; j < 4; j++) {
                    mma_bf16(acc[i][j], ah0, ah1, ah2, ah3, bh0[j], bh1[j]);
                    mma_bf16(acc[i][j], al0, al1, al2, al3, bh0[j], bh1[j]);
                    mma_bf16(acc[i][j], ah0, ah1, ah2, ah3, bl0[j], bl1[j]);
                }
            }
        }
        __syncthreads();
    }

    // epilogue: (c0,c1)=(qr,2qc..2qc+1), (c2,c3)=(qr+8,..) -> float2 stores
#pragma unroll
    for (int i = 0; i < 4; i++) {
        const int row0 = bm + wm + i * 16 + qr;
#pragma unroll
        for (int j = 0; j < 4; j++) {
            const int cc = bn + wn + j * 8 + qc * 2;
            if (cc < N) {
#pragma unroll
                for (int half = 0; half < 2; half++) {
                    const int rr = row0 + half * 8;
                    float v0 = acc[i][j][half * 2];
                    float v1 = acc[i][j][half * 2 + 1];
                    if (epi == 1) {
                        v0 += bias[cc];
                        v1 += bias[cc + 1];
                        v0 = (v0 > 15.f) ? v0 : __logf(1.f + __expf(v0));
                        v1 = (v1 > 15.f) ? v1 : __logf(1.f + __expf(v1));
                    }
                    *reinterpret_cast<float2*>(&Cout[(size_t)rr * ldc + cc]) =
                        make_float2(v0, v1);
                }
            }
        }
    }
}

// ---------------------------------------------------------------------------
// One-shot split of x + all weights into bf16 hi/lo. 4 elems per thread.
// ---------------------------------------------------------------------------
__global__ __launch_bounds__(256) void split_all(
    const float* __restrict__ x,   const float* __restrict__ Win,
    const float* __restrict__ Wx0, const float* __restrict__ Wx1,
    const float* __restrict__ Wdt0,const float* __restrict__ Wdt1,
    const float* __restrict__ Wout)
{
    const size_t O0 = 0;
    const size_t O1 = O0 + N_X;
    const size_t O2 = O1 + N_WIN;
    const size_t O3 = O2 + N_WX;
    const size_t O4 = O3 + N_WX;
    const size_t O5 = O4 + N_WDT;
    const size_t O6 = O5 + N_WDT;
    const size_t O7 = O6 + N_WOUT;

    size_t i = ((size_t)blockIdx.x * 256 + threadIdx.x) * 4;
    if (i >= O7) return;

    const float* src; __nv_bfloat16 *ph, *pl; size_t off;
    if      (i < O1) { src = x;    ph = g_xh;            pl = g_xl;            off = O0; }
    else if (i < O2) { src = Win;  ph = g_Winh;          pl = g_Winl;          off = O1; }
    else if (i < O3) { src = Wx0;  ph = g_Wxh;           pl = g_Wxl;           off = O2; }
    else if (i < O4) { src = Wx1;  ph = g_Wxh + N_WX;    pl = g_Wxl + N_WX;    off = O3; }
    else if (i < O5) { src = Wdt0; ph = g_Wdth;          pl = g_Wdtl;          off = O4; }
    else if (i < O6) { src = Wdt1; ph = g_Wdth + N_WDT;  pl = g_Wdtl + N_WDT;  off = O5; }
    else             { src = Wout; ph = g_Wouth;         pl = g_Woutl;         off = O6; }

    size_t k = i - off;
    float4 v = *reinterpret_cast<const float4*>(src + k);
    __nv_bfloat16 h[4], l[4];
    s1(v.x, h[0], l[0]); s1(v.y, h[1], l[1]);
    s1(v.z, h[2], l[2]); s1(v.w, h[3], l[3]);
    *reinterpret_cast<uint2*>(ph + k) = *reinterpret_cast<uint2*>(h);
    *reinterpret_cast<uint2*>(pl + k) = *reinterpret_cast<uint2*>(l);
}

// ---------------------------------------------------------------------------
// Reduce split-K partials for both dirs + bf16 split, float4-vectorized.
// One thread = 4 consecutive elements of one dir.
// ---------------------------------------------------------------------------
__global__ void reduce_splits(const float* __restrict__ part,
                              float* __restrict__ outp, int n1)
{
    size_t q = (size_t)blockIdx.x * blockDim.x + threadIdx.x;   // float4 index
    const size_t g1 = (size_t)n1 / 4;
    if (q >= 2 * g1) return;
    const int dir = (int)(q / g1);
    const size_t i = (size_t)dir * n1 + (q - (size_t)dir * g1) * 4;
    const size_t ii = i - (size_t)dir * n1;
    const float* p = part + (size_t)dir * SPLITS * n1;
    float4 s = make_float4(0.f, 0.f, 0.f, 0.f);
#pragma unroll
    for (int j = 0; j < SPLITS; j++) {
        float4 v = *reinterpret_cast<const float4*>(p + (size_t)j * n1 + ii);
        s.x += v.x; s.y += v.y; s.z += v.z; s.w += v.w;
    }
    *reinterpret_cast<float4*>(outp + i) = s;
    __nv_bfloat16 h[4], l[4];
    s1(s.x, h[0], l[0]); s1(s.y, h[1], l[1]);
    s1(s.z, h[2], l[2]); s1(s.w, h[3], l[3]);
    *reinterpret_cast<uint2*>(g_dbch + i) = *reinterpret_cast<uint2*>(h);
    *reinterpret_cast<uint2*>(g_dbcl + i) = *reinterpret_cast<uint2*>(l);
}

// ---------------------------------------------------------------------------
// Sum the 2 out-GEMM split-K partials (vectorized float4).
// ---------------------------------------------------------------------------
__global__ void reduce_out(const float* __restrict__ part,
                           float* __restrict__ outp)
{
    size_t i = ((size_t)blockIdx.x * 256 + threadIdx.x) * 4;
    if (i >= NOUT) return;
    float4 a = *reinterpret_cast<const float4*>(part + i);
    float4 b = *reinterpret_cast<const float4*>(part + NOUT + i);
    *reinterpret_cast<float4*>(outp + i) =
        make_float4(a.x + b.x, a.y + b.y, a.z + b.z, a.w + b.w);
}

// ---------------------------------------------------------------------------
// Causal depthwise conv (K=4) + SiLU, float4 over channels (4 e per thread).
// Per-channel fmaf order identical to the scalar version.
// ---------------------------------------------------------------------------
__global__ __launch_bounds__(256) void conv_silu_kernel(
    const float* __restrict__ xz,
    const float* __restrict__ w0, const float* __restrict__ cb0,
    const float* __restrict__ w1, const float* __restrict__ cb1,
    float* __restrict__ xc)
{
    const size_t G = NED / 4;                      // groups per dir
    size_t idx = (size_t)blockIdx.x * blockDim.x + threadIdx.x;
    if (idx >= 2 * G) return;
    const int dir = (int)(idx / G);
    size_t loc = idx - (size_t)dir * G;
    const int eg = (int)(loc % (ED / 4));
    const int t  = (int)((loc / (ED / 4)) % LSEQ);
    const int b  = (int)(loc / ((size_t)(ED / 4) * LSEQ));
    const int e  = eg * 4;
    const float* w  = dir ? w1  : w0;
    const float* cb = dir ? cb1 : cb0;

    // taps: channel e+c owns w[4*(e+c) .. 4*(e+c)+3] (contiguous float4)
    float4 tp0 = *reinterpret_cast<const float4*>(w + 4 * (e + 0));
    float4 tp1 = *reinterpret_cast<const float4*>(w + 4 * (e + 1));
    float4 tp2 = *reinterpret_cast<const float4*>(w + 4 * (e + 2));
    float4 tp3 = *reinterpret_cast<const float4*>(w + 4 * (e + 3));
    const float tap0[4] = {tp0.x, tp0.y, tp0.z, tp0.w};
    const float tap1[4] = {tp1.x, tp1.y, tp1.z, tp1.w};
    const float tap2[4] = {tp2.x, tp2.y, tp2.z, tp2.w};
    const float tap3[4] = {tp3.x, tp3.y, tp3.z, tp3.w};

    float4 acc = *reinterpret_cast<const float4*>(cb + e);
#pragma unroll
    for (int i = 0; i < 4; i++) {
        int tau = t - 3 + i;
        if (tau >= 0) {
            int tt = dir ? (LSEQ - 1 - tau) : tau;
            float4 xv = *reinterpret_cast<const float4*>(
                xz + ((size_t)b * LSEQ + tt) * (2 * ED) + e);
            acc.x = fmaf(tap0[i], xv.x, acc.x);
            acc.y = fmaf(tap1[i], xv.y, acc.y);
            acc.z = fmaf(tap2[i], xv.z, acc.z);
            acc.w = fmaf(tap3[i], xv.w, acc.w);
        }
    }
    float4 val;
    val.x = acc.x * sigmoidf_(acc.x);
    val.y = acc.y * sigmoidf_(acc.y);
    val.z = acc.z * sigmoidf_(acc.z);
    val.w = acc.w * sigmoidf_(acc.w);

    const size_t o = (size_t)dir * NED + loc * 4;
    *reinterpret_cast<float4*>(xc + o) = val;
    __nv_bfloat16 h[4], l[4];
    s1(val.x, h[0], l[0]); s1(val.y, h[1], l[1]);
    s1(val.z, h[2], l[2]); s1(val.w, h[3], l[3]);
    *reinterpret_cast<uint2*>(g_xch + o) = *reinterpret_cast<uint2*>(h);
    *reinterpret_cast<uint2*>(g_xcl + o) = *reinterpret_cast<uint2*>(l);
}

// ---------------------------------------------------------------------------
// Combine y = 0.5*(y0+y1) and split to bf16 hi/lo for the output GEMM.
// ---------------------------------------------------------------------------
__global__ __launch_bounds__(256) void combine_kernel(
    const float* __restrict__ y)
{
    size_t i = ((size_t)blockIdx.x * 256 + threadIdx.x) * 4;
    if (i >= NED) return;
    float4 a = *reinterpret_cast<const float4*>(y + i);
    float4 b = *reinterpret_cast<const float4*>(y + NED + i);
    __nv_bfloat16 h[4], l[4];
    s1(0.5f * (a.x + b.x), h[0], l[0]);
    s1(0.5f * (a.y + b.y), h[1], l[1]);
    s1(0.5f * (a.z + b.z), h[2], l[2]);
    s1(0.5f * (a.w + b.w), h[3], l[3]);
    *reinterpret_cast<uint2*>(g_ych + i) = *reinterpret_cast<uint2*>(h);
    *reinterpret_cast<uint2*>(g_ycl + i) = *reinterpret_cast<uint2*>(l);
}

// ---------------------------------------------------------------------------
// Selective scan, both directions in one launch (512 blocks x 128 threads).
// ---------------------------------------------------------------------------
__global__ __launch_bounds__(128) void scan_kernel(
    const float* __restrict__ delta,
    const float* __restrict__ xconv,
    const float* __restrict__ dbc,
    const float* __restrict__ xz,
    const float* __restrict__ A0, const float* __restrict__ A1,
    const float* __restrict__ D0, const float* __restrict__ D1,
    float* __restrict__ y)
{
    const int dir = blockIdx.x >> 8;
    const int rb  = blockIdx.x & 255;
    const int b   = rb >> 6;
    const int ec  = rb & 63;
    const int tid = threadIdx.x;
    const int e = ec * 32 + (tid >> 2);
    const int g = tid & 3;

    const float* dlt  = delta + (size_t)dir * NED;
    const float* xcv  = xconv + (size_t)dir * NED;
    const float* dbcd = dbc + (size_t)dir * NDBC;
    const float* A_log = dir ? A1 : A0;
    const float* Dp    = dir ? D1 : D0;
    float* yo = y + (size_t)dir * NED;

    float4 al = *reinterpret_cast<const float4*>(&A_log[e * NS + g * 4]);
    const float Aa = -__expf(al.x), Ab = -__expf(al.y),
                Ac = -__expf(al.z), Ad = -__expf(al.w);
    const float dp = Dp[e];

    float h0 = 0.f, h1 = 0.f, h2 = 0.f, h3 = 0.f;
    const size_t baseBL = (size_t)b * LSEQ;

    for (int t = 0; t < LSEQ; t++) {
        const size_t row = baseBL + t;
        const float d  = dlt[row * ED + e];
        const float xv = xcv[row * ED + e];
        const int   tt = dir ? (LSEQ - 1 - t) : t;
        const float zv = xz[(baseBL + tt) * (2 * ED) + ED + e];
        float4 Bv = *reinterpret_cast<const float4*>(&dbcd[row * KX + DTR + g * 4]);
        float4 Cv = *reinterpret_cast<const float4*>(&dbcd[row * KX + DTR + NS + g * 4]);

        const float dx = d * xv;
        h0 = fmaf(__expf(d * Aa), h0, dx * Bv.x);
        h1 = fmaf(__expf(d * Ab), h1, dx * Bv.y);
        h2 = fmaf(__expf(d * Ac), h2, dx * Bv.z);
        h3 = fmaf(__expf(d * Ad), h3, dx * Bv.w);

        float yp = h0 * Cv.x + h1 * Cv.y + h2 * Cv.z + h3 * Cv.w;
        yp += __shfl_xor_sync(0xffffffffu, yp, 1);
        yp += __shfl_xor_sync(0xffffffffu, yp, 2);

        if (g == 0) {
            float yt  = yp + dp * xv;
            float val = yt * (zv * sigmoidf_(zv));
            size_t orow = dir ? (baseBL + (LSEQ - 1 - t)) : row;
            yo[orow * ED + e] = val;
        }
    }
}

// ---------------------------------------------------------------------------
extern "C" void kernel_launch(void* const* d_in, const int* in_sizes, int n_in,
                              void* d_out, int out_size)
{
    (void)in_sizes; (void)n_in; (void)out_size;
    const float* x     = (const float*)d_in[0];
    const float* W_in  = (const float*)d_in[1];
    const float* cw0   = (const float*)d_in[2];
    const float* cb0   = (const float*)d_in[3];
    const float* Wx0   = (const float*)d_in[4];
    const float* Wdt0  = (const float*)d_in[5];
    const float* bdt0  = (const float*)d_in[6];
    const float* Al0   = (const float*)d_in[7];
    const float* Dp0   = (const float*)d_in[8];
    const float* cw1   = (const float*)d_in[9];
    const float* cb1   = (const float*)d_in[10];
    const float* Wx1   = (const float*)d_in[11];
    const float* Wdt1  = (const float*)d_in[12];
    const float* bdt1  = (const float*)d_in[13];
    const float* Al1   = (const float*)d_in[14];
    const float* Dp1   = (const float*)d_in[15];
    const float* W_out = (const float*)d_in[16];
    float* out = (float*)d_out;

    cudaFuncSetAttribute(tgemm_bf16,
                         cudaFuncAttributeMaxDynamicSharedMemorySize, 65536);

    float *p_xz, *p_xc, *p_dbc, *p_dbcp, *p_delta, *p_y;
    cudaGetSymbolAddress((void**)&p_xz,    g_xz);
    cudaGetSymbolAddress((void**)&p_xc,    g_xconv);
    cudaGetSymbolAddress((void**)&p_dbc,   g_dbc);
    cudaGetSymbolAddress((void**)&p_dbcp,  g_dbcp);
    cudaGetSymbolAddress((void**)&p_delta, g_delta);
    cudaGetSymbolAddress((void**)&p_y,     g_y);

    __nv_bfloat16 *xh, *xl, *Winh, *Winl, *Wxh, *Wxl, *Wdth, *Wdtl;
    __nv_bfloat16 *Wouth, *Woutl, *xch, *xcl, *dbch, *dbcl, *ych, *ycl;
    cudaGetSymbolAddress((void**)&xh,    g_xh);
    cudaGetSymbolAddress((void**)&xl,    g_xl);
    cudaGetSymbolAddress((void**)&Winh,  g_Winh);
    cudaGetSymbolAddress((void**)&Winl,  g_Winl);
    cudaGetSymbolAddress((void**)&Wxh,   g_Wxh);
    cudaGetSymbolAddress((void**)&Wxl,   g_Wxl);
    cudaGetSymbolAddress((void**)&Wdth,  g_Wdth);
    cudaGetSymbolAddress((void**)&Wdtl,  g_Wdtl);
    cudaGetSymbolAddress((void**)&Wouth, g_Wouth);
    cudaGetSymbolAddress((void**)&Woutl, g_Woutl);
    cudaGetSymbolAddress((void**)&xch,   g_xch);
    cudaGetSymbolAddress((void**)&xcl,   g_xcl);
    cudaGetSymbolAddress((void**)&dbch,  g_dbch);
    cudaGetSymbolAddress((void**)&dbcl,  g_dbcl);
    cudaGetSymbolAddress((void**)&ych,   g_ych);
    cudaGetSymbolAddress((void**)&ycl,   g_ycl);

    // A) one-shot split of x + all weights
    const size_t tot4 = (N_X + N_WIN + 2*N_WX + 2*N_WDT + N_WOUT) / 4;
    split_all<<<(unsigned)((tot4 + 255) / 256), 256>>>(
        x, W_in, Wx0, Wx1, Wdt0, Wdt1, W_out);

    // 0) xz = x @ W_in.T : (2048 x 4096), K=1024
    tgemm_bf16<<<dim3(2 * ED / 128, MROWS / 128, 1), 256, 65536>>>(
        xh, xl, DM, 0, Winh, Winl, Winh, Winl, DM,
        p_xz, 2 * ED, 0, MROWS, 2 * ED, DM, DM, 1, 0, nullptr, nullptr);

    // 1) conv + silu (float4 over channels), both dirs
    conv_silu_kernel<<<(unsigned)((2 * (NED / 4) + 255) / 256), 256>>>(
        p_xz, cw0, cb0, cw1, cb1, p_xc);

    // 2) dbc partials = xconv @ Wx.T : (2048 x 96), K=2048, split-K x8, both dirs
    tgemm_bf16<<<dim3(1, MROWS / 128, 2 * SPLITS), 256, 65536>>>(
        xch, xcl, ED, NED, Wxh, Wxl, Wxh + N_WX, Wxl + N_WX, ED,
        p_dbcp, KX, (size_t)SPLITS * NDBC,
        MROWS, KX, ED, ED / SPLITS, SPLITS, 0, nullptr, nullptr);

    // 3) reduce partials (+ bf16 split), float4-vectorized
    reduce_splits<<<(unsigned)((2 * (NDBC / 4) + 255) / 256), 256>>>(
        p_dbcp, p_dbc, (int)NDBC);

    // 4) delta = softplus(dbc[:, :64] @ Wdt.T + b_dt), K=64, both dirs
    tgemm_bf16<<<dim3(ED / 128, MROWS / 128, 2), 256, 65536>>>(
        dbch, dbcl, KX, NDBC, Wdth, Wdtl, Wdth + N_WDT, Wdtl + N_WDT, DTR,
        p_delta, ED, NED, MROWS, ED, DTR, DTR, 1, 1, bdt0, bdt1);

    // 5) selective scan, both dirs
    scan_kernel<<<512, 128>>>(p_delta, p_xc, p_dbc, p_xz,
                              Al0, Al1, Dp0, Dp1, p_y);

    // 6) combine y = 0.5*(y0+y1) -> bf16 hi/lo
    combine_kernel<<<(unsigned)((NED / 4 + 255) / 256), 256>>>(p_y);

    // 7) out partials = yc @ W_out.T : (2048 x 1024), K=2048, split-K x2
    tgemm_bf16<<<dim3(DM / 128, MROWS / 128, 2), 256, 65536>>>(
        ych, ycl, ED, 0, Wouth, Woutl, Wouth, Woutl, ED,
        p_delta, DM, 0, MROWS, DM, ED, ED / 2, 2, 0, nullptr, nullptr);

    // 8) out = partial0 + partial1
    reduce_out<<<(unsigned)((NOUT / 4 + 255) / 256), 256>>>(p_delta, out);
}

// round 16
// speedup vs baseline: 1.3917x; 1.3917x over previous
#include <cuda_runtime.h>
#include <cuda_bf16.h>
#include <math.h>

#define B_SZ 4
#define LSEQ 512
#define DM   1024
#define ED   2048
#define NS   16
#define DTR  64
#define KX   96                 // DTR + 2*NS
#define MROWS (B_SZ*LSEQ)       // 2048
#define SPLITS 8
#define NED   ((size_t)MROWS * ED)
#define NDBC  ((size_t)MROWS * KX)
#define NOUT  ((size_t)MROWS * DM)

#define N_X    ((size_t)MROWS * DM)
#define N_WIN  ((size_t)2 * ED * DM)
#define N_WX   ((size_t)KX * ED)
#define N_WDT  ((size_t)ED * DTR)
#define N_WOUT ((size_t)DM * ED)

// ---------------- scratch (static device globals; no runtime allocation) ----
__device__ __align__(16) float g_xz   [(size_t)MROWS * 2 * ED];
__device__ __align__(16) float g_xconv[2 * NED];
__device__ __align__(16) float g_dbc  [2 * NDBC];
__device__ __align__(16) float g_dbcp [2 * (size_t)SPLITS * NDBC];
__device__ __align__(16) float g_delta[2 * NED];   // reused post-scan for out partials
__device__ __align__(16) float g_y    [2 * NED];

// bf16 hi/lo split operands
__device__ __align__(16) __nv_bfloat16 g_xh[N_X],     g_xl[N_X];
__device__ __align__(16) __nv_bfloat16 g_Winh[N_WIN], g_Winl[N_WIN];
__device__ __align__(16) __nv_bfloat16 g_Wxh[2*N_WX], g_Wxl[2*N_WX];
__device__ __align__(16) __nv_bfloat16 g_Wdth[2*N_WDT], g_Wdtl[2*N_WDT];
__device__ __align__(16) __nv_bfloat16 g_Wouth[N_WOUT], g_Woutl[N_WOUT];
__device__ __align__(16) __nv_bfloat16 g_xch[2*NED], g_xcl[2*NED];
__device__ __align__(16) __nv_bfloat16 g_dbch[2*NDBC], g_dbcl[2*NDBC];
__device__ __align__(16) __nv_bfloat16 g_ych[NED], g_ycl[NED];

__device__ __forceinline__ float sigmoidf_(float v) {
    return 1.f / (1.f + __expf(-v));
}

__device__ __forceinline__ void s1(float v, __nv_bfloat16& h, __nv_bfloat16& l) {
    h = __float2bfloat16(v);
    l = __float2bfloat16(v - __bfloat162float(h));
}

// bf16 m16n8k16 MMA (row.col), fp32 accumulate in-place.
__device__ __forceinline__ void mma_bf16(float c[4],
                                         unsigned a0, unsigned a1,
                                         unsigned a2, unsigned a3,
                                         unsigned b0, unsigned b1)
{
    asm volatile(
        "mma.sync.aligned.m16n8k16.row.col.f32.bf16.bf16.f32 "
        "{%0,%1,%2,%3}, {%4,%5,%6,%7}, {%8,%9}, {%0,%1,%2,%3};\n"
        : "+f"(c[0]), "+f"(c[1]), "+f"(c[2]), "+f"(c[3])
        : "r"(a0), "r"(a1), "r"(a2), "r"(a3), "r"(b0), "r"(b1));
}

__device__ __forceinline__ void ldsm_x4(unsigned& r0, unsigned& r1,
                                        unsigned& r2, unsigned& r3, unsigned a)
{
    asm volatile("ldmatrix.sync.aligned.m8n8.x4.shared.b16 {%0,%1,%2,%3}, [%4];"
                 : "=r"(r0), "=r"(r1), "=r"(r2), "=r"(r3) : "r"(a));
}

__device__ __forceinline__ void ldsm_x2(unsigned& r0, unsigned& r1, unsigned a)
{
    asm volatile("ldmatrix.sync.aligned.m8n8.x2.shared.b16 {%0,%1}, [%2];"
                 : "=r"(r0), "=r"(r1) : "r"(a));
}

__device__ __forceinline__ void cpa16(unsigned saddr, const void* g, bool v) {
    asm volatile("cp.async.ca.shared.global [%0], [%1], 16, %2;\n"
                 :: "r"(saddr), "l"(g), "r"(v ? 16 : 0));
}

// ---------------------------------------------------------------------------
// Tensor-core NT GEMM, pre-split bf16 (3-MMA compensated):
//   C[m,n] = sum_k (Ah+Al)[m,k] * (Bh+Bl)[n,k]  (dropping Al*Bl)
// BM=BN=128, BK=32, 256 threads = 8 warps (2x4), warp tile 64x32.
// Double-buffered cp.async staging; ldmatrix fragment loads.
// __launch_bounds__(256,2): cap regs at 128 so 2 CTAs/SM co-reside.
// blockIdx.z = dir*zdiv + split s. epi1 = softplus(v+bias[n]).
// ---------------------------------------------------------------------------
__global__ __launch_bounds__(256, 2) void tgemm_bf16(
    const __nv_bfloat16* __restrict__ Ahp, const __nv_bfloat16* __restrict__ Alp,
    int lda, size_t sAdir,
    const __nv_bfloat16* __restrict__ Bh0, const __nv_bfloat16* __restrict__ Bl0,
    const __nv_bfloat16* __restrict__ Bh1, const __nv_bfloat16* __restrict__ Bl1,
    int ldb,
    float* __restrict__ C, int ldc, size_t sCdir,
    int M, int N, int Ktot, int ksz, int zdiv,
    int epi, const float* __restrict__ bias0, const float* __restrict__ bias1)
{
    extern __shared__ unsigned smem[];   // 2 x 32KB

    const int bm  = blockIdx.y * 128;
    const int bn  = blockIdx.x * 128;
    const int dir = blockIdx.z / zdiv;
    const int s   = blockIdx.z % zdiv;
    const int k0  = s * ksz;
    int k1 = k0 + ksz; if (k1 > Ktot) k1 = Ktot;
    const int T = (k1 - k0) >> 5;        // BK=32 tiles

    const __nv_bfloat16* Ah = Ahp + (size_t)dir * sAdir;
    const __nv_bfloat16* Al = Alp + (size_t)dir * sAdir;
    const __nv_bfloat16* Bh = dir ? Bh1 : Bh0;
    const __nv_bfloat16* Bl = dir ? Bl1 : Bl0;
    const float* bias = dir ? bias1 : bias0;
    float* Cout = C + (size_t)dir * sCdir + (size_t)s * (size_t)M * (size_t)ldc;

    const int tid  = threadIdx.x;
    const int warp = tid >> 5, lane = tid & 31;
    const int wm = (warp >> 2) * 64;
    const int wn = (warp & 3) * 32;
    const int qr = lane >> 2;            // 0..7
    const int qc = lane & 3;             // 0..3

    unsigned sbase = (unsigned)__cvta_generic_to_shared(smem);

    auto stage = [&](int kbase, int buf) {
        unsigned base = sbase + buf * 32768;
#pragma unroll
        for (int u = tid; u < 512; u += 256) {
            int row = u >> 2, grp = u & 3;
            int gp = grp ^ ((row >> 1) & 3);
            unsigned so = base + (unsigned)(row * 64 + gp * 16);
            const size_t ka = (size_t)(bm + row) * lda + kbase + grp * 8;
            cpa16(so,          Ah + ka, true);
            cpa16(so +  8192,  Al + ka, true);
            bool bv = (bn + row) < N;
            const size_t kb = (size_t)(bn + row) * ldb + kbase + grp * 8;
            cpa16(so + 16384,  Bh + kb, bv);
            cpa16(so + 24576,  Bl + kb, bv);
        }
        asm volatile("cp.async.commit_group;\n");
    };

    // precomputed ldmatrix byte offsets (within one operand array, kk=0)
    unsigned aoff[4], boff[4];
#pragma unroll
    for (int i = 0; i < 4; i++) {
        int row = wm + i * 16 + (lane & 15);
        int ch  = lane >> 4;                      // 0: k0-7, 1: k8-15
        int g   = ch ^ ((row >> 1) & 3);
        aoff[i] = (unsigned)(row * 64 + g * 16);
    }
#pragma unroll
    for (int j = 0; j < 4; j++) {
        int row = wn + j * 8 + (lane & 7);
        int ch  = (lane >> 3) & 1;
        int g   = ch ^ ((row >> 1) & 3);
        boff[j] = (unsigned)(row * 64 + g * 16);
    }

    float acc[4][4][4];
#pragma unroll
    for (int i = 0; i < 4; i++)
#pragma unroll
        for (int j = 0; j < 4; j++)
#pragma unroll
            for (int r = 0; r < 4; r++) acc[i][j][r] = 0.f;

    stage(k0, 0);

    for (int t = 0; t < T; t++) {
        const int nxt = (t + 1 < T) ? t + 1 : t;
        stage(k0 + nxt * 32, (t + 1) & 1);
        asm volatile("cp.async.wait_group 1;\n");
        __syncthreads();

        const unsigned Ab = sbase + (t & 1) * 32768;

#pragma unroll
        for (int kk = 0; kk < 2; kk++) {
            const unsigned kx = kk * 32;          // chunk 0/1 -> 2/3 via XOR
            unsigned bh0[4], bh1[4], bl0[4], bl1[4];
#pragma unroll
            for (int j = 0; j < 4; j++) {
                ldsm_x2(bh0[j], bh1[j], Ab + 16384 + (boff[j] ^ kx));
                ldsm_x2(bl0[j], bl1[j], Ab + 24576 + (boff[j] ^ kx));
            }
#pragma unroll
            for (int i = 0; i < 4; i++) {
                unsigned ah0, ah1, ah2, ah3, al0, al1, al2, al3;
                ldsm_x4(ah0, ah1, ah2, ah3, Ab + (aoff[i] ^ kx));
                ldsm_x4(al0, al1, al2, al3, Ab + 8192 + (aoff[i] ^ kx));
#pragma unroll
                for (int j = 0; j < 4; j++) {
                    mma_bf16(acc[i][j], ah0, ah1, ah2, ah3, bh0[j], bh1[j]);
                    mma_bf16(acc[i][j], al0, al1, al2, al3, bh0[j], bh1[j]);
                    mma_bf16(acc[i][j], ah0, ah1, ah2, ah3, bl0[j], bl1[j]);
                }
            }
        }
        __syncthreads();
    }

    // epilogue: (c0,c1)=(qr,2qc..2qc+1), (c2,c3)=(qr+8,..) -> float2 stores
#pragma unroll
    for (int i = 0; i < 4; i++) {
        const int row0 = bm + wm + i * 16 + qr;
#pragma unroll
        for (int j = 0; j < 4; j++) {
            const int cc = bn + wn + j * 8 + qc * 2;
            if (cc < N) {
#pragma unroll
                for (int half = 0; half < 2; half++) {
                    const int rr = row0 + half * 8;
                    float v0 = acc[i][j][half * 2];
                    float v1 = acc[i][j][half * 2 + 1];
                    if (epi == 1) {
                        v0 += bias[cc];
                        v1 += bias[cc + 1];
                        v0 = (v0 > 15.f) ? v0 : __logf(1.f + __expf(v0));
                        v1 = (v1 > 15.f) ? v1 : __logf(1.f + __expf(v1));
                    }
                    *reinterpret_cast<float2*>(&Cout[(size_t)rr * ldc + cc]) =
                        make_float2(v0, v1);
                }
            }
        }
    }
}

// ---------------------------------------------------------------------------
// One-shot split of x + all weights into bf16 hi/lo. 4 elems per thread.
// ---------------------------------------------------------------------------
__global__ __launch_bounds__(256) void split_all(
    const float* __restrict__ x,   const float* __restrict__ Win,
    const float* __restrict__ Wx0, const float* __restrict__ Wx1,
    const float* __restrict__ Wdt0,const float* __restrict__ Wdt1,
    const float* __restrict__ Wout)
{
    const size_t O0 = 0;
    const size_t O1 = O0 + N_X;
    const size_t O2 = O1 + N_WIN;
    const size_t O3 = O2 + N_WX;
    const size_t O4 = O3 + N_WX;
    const size_t O5 = O4 + N_WDT;
    const size_t O6 = O5 + N_WDT;
    const size_t O7 = O6 + N_WOUT;

    size_t i = ((size_t)blockIdx.x * 256 + threadIdx.x) * 4;
    if (i >= O7) return;

    const float* src; __nv_bfloat16 *ph, *pl; size_t off;
    if      (i < O1) { src = x;    ph = g_xh;            pl = g_xl;            off = O0; }
    else if (i < O2) { src = Win;  ph = g_Winh;          pl = g_Winl;          off = O1; }
    else if (i < O3) { src = Wx0;  ph = g_Wxh;           pl = g_Wxl;           off = O2; }
    else if (i < O4) { src = Wx1;  ph = g_Wxh + N_WX;    pl = g_Wxl + N_WX;    off = O3; }
    else if (i < O5) { src = Wdt0; ph = g_Wdth;          pl = g_Wdtl;          off = O4; }
    else if (i < O6) { src = Wdt1; ph = g_Wdth + N_WDT;  pl = g_Wdtl + N_WDT;  off = O5; }
    else             { src = Wout; ph = g_Wouth;         pl = g_Woutl;         off = O6; }

    size_t k = i - off;
    float4 v = *reinterpret_cast<const float4*>(src + k);
    __nv_bfloat16 h[4], l[4];
    s1(v.x, h[0], l[0]); s1(v.y, h[1], l[1]);
    s1(v.z, h[2], l[2]); s1(v.w, h[3], l[3]);
    *reinterpret_cast<uint2*>(ph + k) = *reinterpret_cast<uint2*>(h);
    *reinterpret_cast<uint2*>(pl + k) = *reinterpret_cast<uint2*>(l);
}

// ---------------------------------------------------------------------------
// Reduce split-K partials for both dirs + bf16 split of result.
// ---------------------------------------------------------------------------
__global__ void reduce_splits(const float* __restrict__ part,
                              float* __restrict__ outp, int n1)
{
    int i = blockIdx.x * blockDim.x + threadIdx.x;
    if (i >= 2 * n1) return;
    int dir = i / n1, ii = i - dir * n1;
    const float* p = part + (size_t)dir * SPLITS * n1;
    float s = 0.f;
#pragma unroll
    for (int j = 0; j < SPLITS; j++) s += p[(size_t)j * n1 + ii];
    outp[i] = s;
    s1(s, g_dbch[i], g_dbcl[i]);
}

// ---------------------------------------------------------------------------
// Sum the 2 out-GEMM split-K partials (vectorized float4).
// ---------------------------------------------------------------------------
__global__ void reduce_out(const float* __restrict__ part,
                           float* __restrict__ outp)
{
    size_t i = ((size_t)blockIdx.x * 256 + threadIdx.x) * 4;
    if (i >= NOUT) return;
    float4 a = *reinterpret_cast<const float4*>(part + i);
    float4 b = *reinterpret_cast<const float4*>(part + NOUT + i);
    *reinterpret_cast<float4*>(outp + i) =
        make_float4(a.x + b.x, a.y + b.y, a.z + b.z, a.w + b.w);
}

// ---------------------------------------------------------------------------
// Causal depthwise conv (K=4) + SiLU, both dirs; writes fp32 + bf16 hi/lo.
// ---------------------------------------------------------------------------
__global__ __launch_bounds__(256) void conv_silu_kernel(
    const float* __restrict__ xz,
    const float* __restrict__ w0, const float* __restrict__ cb0,
    const float* __restrict__ w1, const float* __restrict__ cb1,
    float* __restrict__ xc)
{
    size_t idx = (size_t)blockIdx.x * blockDim.x + threadIdx.x;
    if (idx >= 2 * NED) return;
    const int dir = (int)(idx / NED);
    size_t loc = idx - (size_t)dir * NED;
    int e = (int)(loc % ED);
    int t = (int)((loc / ED) % LSEQ);
    int b = (int)(loc / ((size_t)ED * LSEQ));
    const float* w  = dir ? w1  : w0;
    const float* cb = dir ? cb1 : cb0;

    float acc = cb[e];
#pragma unroll
    for (int i = 0; i < 4; i++) {
        int tau = t - 3 + i;
        if (tau >= 0) {
            int tt = dir ? (LSEQ - 1 - tau) : tau;
            acc = fmaf(w[e * 4 + i],
                       xz[((size_t)b * LSEQ + tt) * (2 * ED) + e], acc);
        }
    }
    float val = acc * sigmoidf_(acc);
    xc[idx] = val;
    s1(val, g_xch[idx], g_xcl[idx]);
}

// ---------------------------------------------------------------------------
// Combine y = 0.5*(y0+y1) and split to bf16 hi/lo for the output GEMM.
// ---------------------------------------------------------------------------
__global__ __launch_bounds__(256) void combine_kernel(
    const float* __restrict__ y)
{
    size_t i = ((size_t)blockIdx.x * 256 + threadIdx.x) * 4;
    if (i >= NED) return;
    float4 a = *reinterpret_cast<const float4*>(y + i);
    float4 b = *reinterpret_cast<const float4*>(y + NED + i);
    __nv_bfloat16 h[4], l[4];
    s1(0.5f * (a.x + b.x), h[0], l[0]);
    s1(0.5f * (a.y + b.y), h[1], l[1]);
    s1(0.5f * (a.z + b.z), h[2], l[2]);
    s1(0.5f * (a.w + b.w), h[3], l[3]);
    *reinterpret_cast<uint2*>(g_ych + i) = *reinterpret_cast<uint2*>(h);
    *reinterpret_cast<uint2*>(g_ycl + i) = *reinterpret_cast<uint2*>(l);
}

// ---------------------------------------------------------------------------
// Selective scan, both directions in one launch (512 blocks x 128 threads).
// ---------------------------------------------------------------------------
__global__ __launch_bounds__(128) void scan_kernel(
    const float* __restrict__ delta,
    const float* __restrict__ xconv,
    const float* __restrict__ dbc,
    const float* __restrict__ xz,
    const float* __restrict__ A0, const float* __restrict__ A1,
    const float* __restrict__ D0, const float* __restrict__ D1,
    float* __restrict__ y)
{
    const int dir = blockIdx.x >> 8;
    const int rb  = blockIdx.x & 255;
    const int b   = rb >> 6;
    const int ec  = rb & 63;
    const int tid = threadIdx.x;
    const int e = ec * 32 + (tid >> 2);
    const int g = tid & 3;

    const float* dlt  = delta + (size_t)dir * NED;
    const float* xcv  = xconv + (size_t)dir * NED;
    const float* dbcd = dbc + (size_t)dir * NDBC;
    const float* A_log = dir ? A1 : A0;
    const float* Dp    = dir ? D1 : D0;
    float* yo = y + (size_t)dir * NED;

    float4 al = *reinterpret_cast<const float4*>(&A_log[e * NS + g * 4]);
    const float Aa = -__expf(al.x), Ab = -__expf(al.y),
                Ac = -__expf(al.z), Ad = -__expf(al.w);
    const float dp = Dp[e];

    float h0 = 0.f, h1 = 0.f, h2 = 0.f, h3 = 0.f;
    const size_t baseBL = (size_t)b * LSEQ;

    for (int t = 0; t < LSEQ; t++) {
        const size_t row = baseBL + t;
        const float d  = dlt[row * ED + e];
        const float xv = xcv[row * ED + e];
        const int   tt = dir ? (LSEQ - 1 - t) : t;
        const float zv = xz[(baseBL + tt) * (2 * ED) + ED + e];
        float4 Bv = *reinterpret_cast<const float4*>(&dbcd[row * KX + DTR + g * 4]);
        float4 Cv = *reinterpret_cast<const float4*>(&dbcd[row * KX + DTR + NS + g * 4]);

        const float dx = d * xv;
        h0 = fmaf(__expf(d * Aa), h0, dx * Bv.x);
        h1 = fmaf(__expf(d * Ab), h1, dx * Bv.y);
        h2 = fmaf(__expf(d * Ac), h2, dx * Bv.z);
        h3 = fmaf(__expf(d * Ad), h3, dx * Bv.w);

        float yp = h0 * Cv.x + h1 * Cv.y + h2 * Cv.z + h3 * Cv.w;
        yp += __shfl_xor_sync(0xffffffffu, yp, 1);
        yp += __shfl_xor_sync(0xffffffffu, yp, 2);

        if (g == 0) {
            float yt  = yp + dp * xv;
            float val = yt * (zv * sigmoidf_(zv));
            size_t orow = dir ? (baseBL + (LSEQ - 1 - t)) : row;
            yo[orow * ED + e] = val;
        }
    }
}

// ---------------------------------------------------------------------------
extern "C" void kernel_launch(void* const* d_in, const int* in_sizes, int n_in,
                              void* d_out, int out_size)
{
    (void)in_sizes; (void)n_in; (void)out_size;
    const float* x     = (const float*)d_in[0];
    const float* W_in  = (const float*)d_in[1];
    const float* cw0   = (const float*)d_in[2];
    const float* cb0   = (const float*)d_in[3];
    const float* Wx0   = (const float*)d_in[4];
    const float* Wdt0  = (const float*)d_in[5];
    const float* bdt0  = (const float*)d_in[6];
    const float* Al0   = (const float*)d_in[7];
    const float* Dp0   = (const float*)d_in[8];
    const float* cw1   = (const float*)d_in[9];
    const float* cb1   = (const float*)d_in[10];
    const float* Wx1   = (const float*)d_in[11];
    const float* Wdt1  = (const float*)d_in[12];
    const float* bdt1  = (const float*)d_in[13];
    const float* Al1   = (const float*)d_in[14];
    const float* Dp1   = (const float*)d_in[15];
    const float* W_out = (const float*)d_in[16];
    float* out = (float*)d_out;

    cudaFuncSetAttribute(tgemm_bf16,
                         cudaFuncAttributeMaxDynamicSharedMemorySize, 65536);

    float *p_xz, *p_xc, *p_dbc, *p_dbcp, *p_delta, *p_y;
    cudaGetSymbolAddress((void**)&p_xz,    g_xz);
    cudaGetSymbolAddress((void**)&p_xc,    g_xconv);
    cudaGetSymbolAddress((void**)&p_dbc,   g_dbc);
    cudaGetSymbolAddress((void**)&p_dbcp,  g_dbcp);
    cudaGetSymbolAddress((void**)&p_delta, g_delta);
    cudaGetSymbolAddress((void**)&p_y,     g_y);

    __nv_bfloat16 *xh, *xl, *Winh, *Winl, *Wxh, *Wxl, *Wdth, *Wdtl;
    __nv_bfloat16 *Wouth, *Woutl, *xch, *xcl, *dbch, *dbcl, *ych, *ycl;
    cudaGetSymbolAddress((void**)&xh,    g_xh);
    cudaGetSymbolAddress((void**)&xl,    g_xl);
    cudaGetSymbolAddress((void**)&Winh,  g_Winh);
    cudaGetSymbolAddress((void**)&Winl,  g_Winl);
    cudaGetSymbolAddress((void**)&Wxh,   g_Wxh);
    cudaGetSymbolAddress((void**)&Wxl,   g_Wxl);
    cudaGetSymbolAddress((void**)&Wdth,  g_Wdth);
    cudaGetSymbolAddress((void**)&Wdtl,  g_Wdtl);
    cudaGetSymbolAddress((void**)&Wouth, g_Wouth);
    cudaGetSymbolAddress((void**)&Woutl, g_Woutl);
    cudaGetSymbolAddress((void**)&xch,   g_xch);
    cudaGetSymbolAddress((void**)&xcl,   g_xcl);
    cudaGetSymbolAddress((void**)&dbch,  g_dbch);
    cudaGetSymbolAddress((void**)&dbcl,  g_dbcl);
    cudaGetSymbolAddress((void**)&ych,   g_ych);
    cudaGetSymbolAddress((void**)&ycl,   g_ycl);

    // A) one-shot split of x + all weights
    const size_t tot4 = (N_X + N_WIN + 2*N_WX + 2*N_WDT + N_WOUT) / 4;
    split_all<<<(unsigned)((tot4 + 255) / 256), 256>>>(
        x, W_in, Wx0, Wx1, Wdt0, Wdt1, W_out);

    // 0) xz = x @ W_in.T : (2048 x 4096), K=1024
    tgemm_bf16<<<dim3(2 * ED / 128, MROWS / 128, 1), 256, 65536>>>(
        xh, xl, DM, 0, Winh, Winl, Winh, Winl, DM,
        p_xz, 2 * ED, 0, MROWS, 2 * ED, DM, DM, 1, 0, nullptr, nullptr);

    // 1) conv + silu (writes fp32 + bf16 hi/lo), both dirs
    conv_silu_kernel<<<(unsigned)((2 * NED + 255) / 256), 256>>>(
        p_xz, cw0, cb0, cw1, cb1, p_xc);

    // 2) dbc partials = xconv @ Wx.T : (2048 x 96), K=2048, split-K x8, both dirs
    tgemm_bf16<<<dim3(1, MROWS / 128, 2 * SPLITS), 256, 65536>>>(
        xch, xcl, ED, NED, Wxh, Wxl, Wxh + N_WX, Wxl + N_WX, ED,
        p_dbcp, KX, (size_t)SPLITS * NDBC,
        MROWS, KX, ED, ED / SPLITS, SPLITS, 0, nullptr, nullptr);

    // 3) reduce partials (+ bf16 split)
    reduce_splits<<<(unsigned)((2 * NDBC + 255) / 256), 256>>>(
        p_dbcp, p_dbc, (int)NDBC);

    // 4) delta = softplus(dbc[:, :64] @ Wdt.T + b_dt), K=64, both dirs
    tgemm_bf16<<<dim3(ED / 128, MROWS / 128, 2), 256, 65536>>>(
        dbch, dbcl, KX, NDBC, Wdth, Wdtl, Wdth + N_WDT, Wdtl + N_WDT, DTR,
        p_delta, ED, NED, MROWS, ED, DTR, DTR, 1, 1, bdt0, bdt1);

    // 5) selective scan, both dirs
    scan_kernel<<<512, 128>>>(p_delta, p_xc, p_dbc, p_xz,
                              Al0, Al1, Dp0, Dp1, p_y);

    // 6) combine y = 0.5*(y0+y1) -> bf16 hi/lo
    combine_kernel<<<(unsigned)((NED / 4 + 255) / 256), 256>>>(p_y);

    // 7) out partials = yc @ W_out.T : (2048 x 1024), K=2048, split-K x2
    tgemm_bf16<<<dim3(DM / 128, MROWS / 128, 2), 256, 65536>>>(
        ych, ycl, ED, 0, Wouth, Woutl, Wouth, Woutl, ED,
        p_delta, DM, 0, MROWS, DM, ED, ED / 2, 2, 0, nullptr, nullptr);

    // 8) out = partial0 + partial1
    reduce_out<<<(unsigned)((NOUT / 4 + 255) / 256), 256>>>(p_delta, out);
}